// round 16
// baseline (speedup 1.0000x reference)
#include <cuda_runtime.h>
#include <cuda_fp16.h>
#include <cstdint>

#define NN 50000
#define NE 800000
#define NR 16
#define DD 128
#define NP 50048                 // NN padded to 128 (391 blocks)
#define NBLK 391
#define NFLAG (NR * NN)          // 800000 (r,s) pairs ( == NE )
#define NPADMAX (NR * NP)        // 800768 max padded compact rows

// Scratch (device globals; no dynamic allocation allowed).
__device__ float g_sgate[(size_t)NR * NN];         // 3.2 MB gate table
__device__ float g_h1[(size_t)NN * DD];            // 25.6 MB layer-0 output (pre-relu)
__device__ __half g_xh[(size_t)NP * DD];           // 12.8 MB fp16 X (zero-padded)
__device__ __half g_wh[(size_t)(NR + 1) * DD * DD];// 0.55 MB fp16 W^T (n-major)
// Compaction + CSR scratch
__device__ int g_flag[NFLAG];
__device__ int g_scan[NFLAG];
__device__ int g_bsum[1024];
__device__ int g_glist[NPADMAX];
__device__ int g_cidx[NE];
__device__ int g_ecnt[NPADMAX];
__device__ int g_efill[NPADMAX];
__device__ int g_erow[NPADMAX + 1];
__device__ int g_spack[NE];      // (dst << 8) | local_row, row-sorted order
__device__ float g_snorm[NE];    // norm[e], row-sorted order (layer-invariant)
__device__ int g_relstart[NR];
__device__ int g_padoff[NR + 1];
__device__ int g_pblk[NR + 1];
__device__ int g_nblk;

__device__ __forceinline__ uint32_t sptr(const void* p) {
    return (uint32_t)__cvta_generic_to_shared(p);
}
#define LDSM4(r0, r1, r2, r3, addr)                                          \
    asm volatile("ldmatrix.sync.aligned.m8n8.x4.shared.b16 {%0,%1,%2,%3}, [%4];" \
                 : "=r"(r0), "=r"(r1), "=r"(r2), "=r"(r3) : "r"(addr))

// ---------------------------------------------------------------------------
// Compaction + CSR prep (once per call) — unchanged from R12
// ---------------------------------------------------------------------------
__global__ void zero_kernel() {
    int i = blockIdx.x * 256 + threadIdx.x;
    g_glist[i] = 0;
    g_ecnt[i] = 0;
    g_efill[i] = 0;
    if (i < NFLAG) g_flag[i] = 0;
}
__global__ void mark_kernel(const int* __restrict__ src, const int* __restrict__ rel) {
    int e = blockIdx.x * 256 + threadIdx.x;
    g_flag[__ldg(rel + e) * NN + __ldg(src + e)] = 1;
}
__global__ void scan1_kernel(const int* __restrict__ in, int* __restrict__ out, int n) {
    __shared__ int sd[256];
    const int tid = threadIdx.x;
    int base = blockIdx.x * 1024 + tid * 4;
    int f[4], s = 0;
#pragma unroll
    for (int j = 0; j < 4; j++) {
        f[j] = (base + j < n) ? in[base + j] : 0;
        s += f[j];
    }
    sd[tid] = s;
    __syncthreads();
#pragma unroll
    for (int off = 1; off < 256; off <<= 1) {
        int v = (tid >= off) ? sd[tid - off] : 0;
        __syncthreads();
        sd[tid] += v;
        __syncthreads();
    }
    int run = sd[tid] - s;
#pragma unroll
    for (int j = 0; j < 4; j++) {
        if (base + j < n) out[base + j] = run;
        run += f[j];
    }
    if (tid == 255) g_bsum[blockIdx.x] = sd[255];
}
__global__ void scan2_kernel(int nblocks) {
    __shared__ int sd[1024];
    const int tid = threadIdx.x;
    int v0 = (tid < nblocks) ? g_bsum[tid] : 0;
    sd[tid] = v0;
    __syncthreads();
#pragma unroll
    for (int off = 1; off < 1024; off <<= 1) {
        int v = (tid >= off) ? sd[tid - off] : 0;
        __syncthreads();
        sd[tid] += v;
        __syncthreads();
    }
    if (tid < nblocks) g_bsum[tid] = sd[tid] - v0;
}
__global__ void scan3_kernel(int* __restrict__ out, int n, int tail) {
    int i = blockIdx.x * 256 + threadIdx.x;
    if (i < n) out[i] += g_bsum[i >> 10];
    if (i == 0 && tail >= 0) out[n] = tail;
}
__global__ void meta_kernel() {
    if (threadIdx.x != 0) return;
    int total = g_scan[NFLAG - 1] + g_flag[NFLAG - 1];
    int pad = 0;
    for (int r = 0; r < NR; r++) {
        int st = g_scan[r * NN];
        int nx = (r < NR - 1) ? g_scan[(r + 1) * NN] : total;
        g_relstart[r] = st;
        g_padoff[r] = pad;
        g_pblk[r] = pad >> 7;
        pad += ((nx - st + 127) & ~127);
    }
    g_padoff[NR] = pad;
    g_pblk[NR] = pad >> 7;
    g_nblk = pad >> 7;
}
__global__ void buildcidx_kernel(const int* __restrict__ src,
                                 const int* __restrict__ rel) {
    int i = blockIdx.x * 256 + threadIdx.x;
    if (g_flag[i]) {
        int pr = i / NN, ps = i - pr * NN;
        g_glist[g_padoff[pr] + g_scan[i] - g_relstart[pr]] = ps;
    }
    int r = __ldg(rel + i), s = __ldg(src + i);
    int c = g_padoff[r] + g_scan[r * NN + s] - g_relstart[r];
    g_cidx[i] = c;
    atomicAdd(&g_ecnt[c], 1);
}
__global__ void scatter_kernel(const int* __restrict__ dst,
                               const float* __restrict__ norm) {
    int e = blockIdx.x * 256 + threadIdx.x;
    int c = g_cidx[e];
    int pos = g_erow[c] + atomicAdd(&g_efill[c], 1);
    g_spack[pos] = (__ldg(dst + e) << 8) | (c & 127);
    g_snorm[pos] = __ldg(norm + e);
}

// ---------------------------------------------------------------------------
// Merged X pass: one read of x produces the fp16 (relu'd) xh AND the gate
// table. 128 threads = 8 nodes.
// ---------------------------------------------------------------------------
__global__ void gatex_kernel(const float* __restrict__ x,
                             const float* __restrict__ gw, int relu) {
    __shared__ float sx[8][132];
    __shared__ float sg[16][132];
    const int tid = threadIdx.x;
    const int nb = blockIdx.x * 8;                   // grid = NP/8 (covers padding)
#pragma unroll
    for (int i = 0; i < 4; i++) {
        int l = tid + i * 128;
        int r = l >> 5, c = l & 31;
        *(float4*)&sg[r][c * 4] = __ldg((const float4*)gw + r * 32 + c);
    }
#pragma unroll
    for (int i = 0; i < 2; i++) {
        int l = tid + i * 128;
        int n = l >> 5, c = l & 31;
        float4 v = make_float4(0.f, 0.f, 0.f, 0.f);
        if (nb + n < NN) v = __ldg((const float4*)x + (size_t)(nb + n) * 32 + c);
        if (relu) {
            v.x = fmaxf(v.x, 0.f); v.y = fmaxf(v.y, 0.f);
            v.z = fmaxf(v.z, 0.f); v.w = fmaxf(v.w, 0.f);
        }
        *(float4*)&sx[n][c * 4] = v;
    }
    __syncthreads();
    // xh store (fp16 rn), covers padded rows with zeros
#pragma unroll
    for (int i = 0; i < 2; i++) {
        int l = tid + i * 128;
        int n = l >> 5, c = l & 31;
        float4 v = *(float4*)&sx[n][c * 4];
        __half2 h01 = __floats2half2_rn(v.x, v.y);
        __half2 h23 = __floats2half2_rn(v.z, v.w);
        uint2 o;
        o.x = *(uint32_t*)&h01;
        o.y = *(uint32_t*)&h23;
        ((uint2*)g_xh)[(size_t)(nb + n) * 32 + c] = o;
    }
    // gate dot products (fp32, unchanged numerics)
    const int node = tid >> 4, rel = tid & 15;
    float d = 0.f;
#pragma unroll
    for (int k = 0; k < 32; k++) {
        float4 a = *(float4*)&sx[node][k * 4];
        float4 g = *(float4*)&sg[rel][k * 4];
        d += a.x * g.x + a.y * g.y + a.z * g.z + a.w * g.w;
    }
    if (nb + node < NN)
        g_sgate[(size_t)rel * NN + nb + node] = 1.f / (1.f + __expf(-d));
}

// W pre-pass (TRANSPOSED, fp16): g_wh[r][n][k] = fp16( W[r][k][n] ); r=16 -> loop_w.
__global__ void wcvt_kernel(const float* __restrict__ Wr,
                            const float* __restrict__ loopw) {
    int i = blockIdx.x * 256 + threadIdx.x;          // grid = 17*4096/256 = 272
    int r = i >> 12, rem = i & 4095;
    int n = rem >> 5, kq = rem & 31, k = kq * 4;
    const float* src = (r < NR) ? (Wr + (size_t)r * DD * DD) : loopw;
    float v0 = __ldg(src + (size_t)(k + 0) * DD + n);
    float v1 = __ldg(src + (size_t)(k + 1) * DD + n);
    float v2 = __ldg(src + (size_t)(k + 2) * DD + n);
    float v3 = __ldg(src + (size_t)(k + 3) * DD + n);
    __half2 h01 = __floats2half2_rn(v0, v1);
    __half2 h23 = __floats2half2_rn(v2, v3);
    uint2 o;
    o.x = *(uint32_t*)&h01;
    o.y = *(uint32_t*)&h23;
    ((uint2*)g_wh)[(size_t)r * 4096 + n * 32 + kq] = o;
}

// ---------------------------------------------------------------------------
// Unified GEMM: 128x128x128 fp16 tile (fp32 accum), cp.async 3-buffer
// pipeline (4 stages of k32), ldmatrix fragments, mma.m16n8k16.
// Block j < NBLK: self-loop tile (y += X@loop_w + bias). Else: data tile +
// fused edge scatter. Smem stride 40 halves (80 B): ldmatrix conflict-free.
// ---------------------------------------------------------------------------
#define HSTR 40
#define HS (128 * HSTR)          // 5120 halves per stage buffer
#define NSTG 3
#define GEMM_SMEM 68096          // max(3*2*HS*2 = 61440, 128*132*4 + 512)

__global__ void __launch_bounds__(256, 2)
gemm_all_kernel(const float* __restrict__ bias, float* __restrict__ y) {
    extern __shared__ float sm[];
    __half* sA = (__half*)sm;
    __half* sB = sA + NSTG * HS;
    const int tid = threadIdx.x;
    const int j = blockIdx.x;
    const bool is_loop = j < NBLK;
    int r, rowbase;
    if (is_loop) {
        r = NR;
        rowbase = j * 128;
    } else {
        int jj = j - NBLK;
        if (jj >= g_nblk) return;
        r = NR - 1;
#pragma unroll
        for (int q = NR - 1; q > 0; q--)
            if (jj < g_pblk[q]) r = q - 1;
        rowbase = jj * 128;
    }
    const __half* Wp = g_wh + (size_t)r * DD * DD;

    int ga[2];
#pragma unroll
    for (int i = 0; i < 2; i++) {
        int xr = (tid >> 2) + i * 64;
        ga[i] = is_loop ? (rowbase + xr) : __ldg(&g_glist[rowbase + xr]);
    }
    const int c4 = tid & 3;
    float acc[2][8][4];
#pragma unroll
    for (int mt = 0; mt < 2; mt++)
#pragma unroll
        for (int nt = 0; nt < 8; nt++)
#pragma unroll
            for (int q = 0; q < 4; q++) acc[mt][nt][q] = 0.f;

    auto issue = [&](int s, int buf) {
#pragma unroll
        for (int i = 0; i < 2; i++) {
            const char* srcp = (const char*)g_xh + (size_t)ga[i] * 256 + s * 64 + c4 * 16;
            uint32_t dstp = sptr(sA + buf * HS + ((tid >> 2) + i * 64) * HSTR + c4 * 8);
            asm volatile("cp.async.cg.shared.global [%0], [%1], 16;"
                         :: "r"(dstp), "l"(srcp) : "memory");
        }
#pragma unroll
        for (int i = 0; i < 2; i++) {
            int wrow = (tid >> 2) + i * 64;
            const char* srcp = (const char*)Wp + (size_t)wrow * 256 + s * 64 + c4 * 16;
            uint32_t dstp = sptr(sB + buf * HS + wrow * HSTR + c4 * 8);
            asm volatile("cp.async.cg.shared.global [%0], [%1], 16;"
                         :: "r"(dstp), "l"(srcp) : "memory");
        }
    };
    issue(0, 0);
    asm volatile("cp.async.commit_group;" ::: "memory");
    issue(1, 1);
    asm volatile("cp.async.commit_group;" ::: "memory");

    const int warp = tid >> 5, lane = tid & 31;
    const int g = lane >> 2, t = lane & 3;
    const int mbase = (warp >> 1) * 32;
    const int nbase = (warp & 1) * 64;
    // ldmatrix lane->address components (see fragment mapping notes)
    const int aRow = mbase + (lane & 15);
    const int aK   = (lane >> 4) * 8;
    const int bRow = nbase + (lane & 7) + (lane >> 4) * 8;
    const int bK   = ((lane >> 3) & 1) * 8;

#pragma unroll
    for (int s = 0; s < 4; s++) {
        if (s < 3) asm volatile("cp.async.wait_group 1;" ::: "memory");
        else       asm volatile("cp.async.wait_group 0;" ::: "memory");
        __syncthreads();
        if (s + 2 < 4) {
            issue(s + 2, (s + 2) % 3);
            asm volatile("cp.async.commit_group;" ::: "memory");
        }
        const uint32_t sxb = sptr(sA + (s % 3) * HS);
        const uint32_t swb = sptr(sB + (s % 3) * HS);
#pragma unroll
        for (int kk = 0; kk < 2; kk++) {
            const int k0 = kk * 16;
            uint32_t a[2][4];
#pragma unroll
            for (int mt = 0; mt < 2; mt++) {
                uint32_t ad = sxb + ((aRow + mt * 16) * HSTR + k0 + aK) * 2;
                LDSM4(a[mt][0], a[mt][1], a[mt][2], a[mt][3], ad);
            }
#pragma unroll
            for (int p = 0; p < 4; p++) {            // n-tile pairs (2p, 2p+1)
                uint32_t b0a, b1a, b0b, b1b;
                uint32_t bd = swb + ((bRow + p * 16) * HSTR + k0 + bK) * 2;
                LDSM4(b0a, b1a, b0b, b1b, bd);
#pragma unroll
                for (int mt = 0; mt < 2; mt++) {
                    asm volatile(
                        "mma.sync.aligned.m16n8k16.row.col.f32.f16.f16.f32 "
                        "{%0,%1,%2,%3}, {%4,%5,%6,%7}, {%8,%9}, {%0,%1,%2,%3};\n"
                        : "+f"(acc[mt][2 * p][0]), "+f"(acc[mt][2 * p][1]),
                          "+f"(acc[mt][2 * p][2]), "+f"(acc[mt][2 * p][3])
                        : "r"(a[mt][0]), "r"(a[mt][1]), "r"(a[mt][2]),
                          "r"(a[mt][3]), "r"(b0a), "r"(b1a));
                    asm volatile(
                        "mma.sync.aligned.m16n8k16.row.col.f32.f16.f16.f32 "
                        "{%0,%1,%2,%3}, {%4,%5,%6,%7}, {%8,%9}, {%0,%1,%2,%3};\n"
                        : "+f"(acc[mt][2 * p + 1][0]), "+f"(acc[mt][2 * p + 1][1]),
                          "+f"(acc[mt][2 * p + 1][2]), "+f"(acc[mt][2 * p + 1][3])
                        : "r"(a[mt][0]), "r"(a[mt][1]), "r"(a[mt][2]),
                          "r"(a[mt][3]), "r"(b0b), "r"(b1b));
                }
            }
        }
    }

    if (is_loop) {
        // y += X@loop_w + bias (y pre-zeroed; atomics so ordering is free)
#pragma unroll
        for (int mt = 0; mt < 2; mt++) {
            int rA = rowbase + mbase + mt * 16 + g;
#pragma unroll
            for (int nt = 0; nt < 8; nt++) {
                int col = nbase + nt * 8 + 2 * t;
                float ba = __ldg(bias + col), bb = __ldg(bias + col + 1);
                if (rA < NN)
                    asm volatile("red.global.add.v2.f32 [%0], {%1,%2};"
                                 :: "l"(y + (size_t)rA * DD + col),
                                    "f"(acc[mt][nt][0] + ba), "f"(acc[mt][nt][1] + bb)
                                 : "memory");
                if (rA + 8 < NN)
                    asm volatile("red.global.add.v2.f32 [%0], {%1,%2};"
                                 :: "l"(y + (size_t)(rA + 8) * DD + col),
                                    "f"(acc[mt][nt][2] + ba), "f"(acc[mt][nt][3] + bb)
                                 : "memory");
            }
        }
        return;
    }

    // ---- Fused scatter epilogue (data tiles) ----
    __syncthreads();                       // all warps done reading smem buffers
    float* st = sm;                        // 128 x 132 fp32 tile (67.6 KB)
    float* rg = sm + 128 * 132;            // 128 per-row gates
#pragma unroll
    for (int mt = 0; mt < 2; mt++) {
        int rloc = mbase + mt * 16 + g;
#pragma unroll
        for (int nt = 0; nt < 8; nt++) {
            int col = nbase + nt * 8 + 2 * t;
            *(float2*)&st[rloc * 132 + col] =
                make_float2(acc[mt][nt][0], acc[mt][nt][1]);
            *(float2*)&st[(rloc + 8) * 132 + col] =
                make_float2(acc[mt][nt][2], acc[mt][nt][3]);
        }
    }
    if (tid < 128)
        rg[tid] = __ldg(&g_sgate[(size_t)r * NN + __ldg(&g_glist[rowbase + tid])]);
    __syncthreads();

    const int ebeg = __ldg(&g_erow[rowbase]);
    const int eend = __ldg(&g_erow[rowbase + 128]);
    int i = ebeg + warp;
    for (; i + 24 < eend; i += 32) {
        int pk[4];
        float sn[4];
#pragma unroll
        for (int u = 0; u < 4; u++) {
            pk[u] = __ldg(&g_spack[i + u * 8]);
            sn[u] = __ldg(&g_snorm[i + u * 8]);
        }
#pragma unroll
        for (int u = 0; u < 4; u++) {
            float wg = sn[u] * rg[pk[u] & 127];
            float4 v = *(float4*)&st[(pk[u] & 127) * 132 + lane * 4];
            float* yp = y + (size_t)(pk[u] >> 8) * DD + lane * 4;
            asm volatile("red.global.add.v4.f32 [%0], {%1,%2,%3,%4};"
                         :: "l"(yp), "f"(v.x * wg), "f"(v.y * wg),
                            "f"(v.z * wg), "f"(v.w * wg)
                         : "memory");
        }
    }
    for (; i < eend; i += 8) {
        int pk = __ldg(&g_spack[i]);
        float wg = __ldg(&g_snorm[i]) * rg[pk & 127];
        float4 v = *(float4*)&st[(pk & 127) * 132 + lane * 4];
        float* yp = y + (size_t)(pk >> 8) * DD + lane * 4;
        asm volatile("red.global.add.v4.f32 [%0], {%1,%2,%3,%4};"
                     :: "l"(yp), "f"(v.x * wg), "f"(v.y * wg),
                        "f"(v.z * wg), "f"(v.w * wg)
                     : "memory");
    }
}

// ---------------------------------------------------------------------------
extern "C" void kernel_launch(void* const* d_in, const int* in_sizes, int n_in,
                              void* d_out, int out_size) {
    const float* h    = (const float*)d_in[0];
    const float* norm = (const float*)d_in[1];
    const float* w0   = (const float*)d_in[2];
    const float* b0   = (const float*)d_in[3];
    const float* lw0  = (const float*)d_in[4];
    const float* gw0  = (const float*)d_in[5];
    const float* w1   = (const float*)d_in[6];
    const float* b1   = (const float*)d_in[7];
    const float* lw1  = (const float*)d_in[8];
    const float* gw1  = (const float*)d_in[9];
    const int*   src  = (const int*)d_in[10];
    const int*   dst  = (const int*)d_in[11];
    const int*   rel  = (const int*)d_in[12];
    float* out = (float*)d_out;

    cudaFuncSetAttribute(gemm_all_kernel,
                         cudaFuncAttributeMaxDynamicSharedMemorySize, GEMM_SMEM);

    float* h1 = nullptr;
    cudaGetSymbolAddress((void**)&h1, g_h1);
    int* scanp = nullptr;
    cudaGetSymbolAddress((void**)&scanp, g_scan);
    int* flagp = nullptr;
    cudaGetSymbolAddress((void**)&flagp, g_flag);
    int* ecntp = nullptr;
    cudaGetSymbolAddress((void**)&ecntp, g_ecnt);
    int* erowp = nullptr;
    cudaGetSymbolAddress((void**)&erowp, g_erow);

    const int NBF = (NFLAG + 1023) / 1024;           // 782
    const int NBE = (NPADMAX + 1023) / 1024;         // 783
    const int all_grid = NBLK + NPADMAX / 128;       // 6647 worst case
    const int gatex_grid = NP / 8;                   // 6256 (covers padding)
    const int wcvt_grid = (NR + 1) * 128 * 32 / 256; // 272 (exact)

    // ---- Compaction + CSR prep (shared by both layers)
    zero_kernel<<<NPADMAX / 256, 256>>>();
    mark_kernel<<<NE / 256, 256>>>(src, rel);
    scan1_kernel<<<NBF, 256>>>(flagp, scanp, NFLAG);
    scan2_kernel<<<1, 1024>>>(NBF);
    scan3_kernel<<<(NFLAG + 255) / 256, 256>>>(scanp, NFLAG, -1);
    meta_kernel<<<1, 32>>>();
    buildcidx_kernel<<<NE / 256, 256>>>(src, rel);
    scan1_kernel<<<NBE, 256>>>(ecntp, erowp, NPADMAX);
    scan2_kernel<<<1, 1024>>>(NBE);
    scan3_kernel<<<(NPADMAX + 255) / 256, 256>>>(erowp, NPADMAX, NE);
    scatter_kernel<<<NE / 256, 256>>>(dst, norm);

    // ---- Layer 0
    cudaMemsetAsync(h1, 0, (size_t)NN * DD * sizeof(float));
    gatex_kernel<<<gatex_grid, 128>>>(h, gw0, 0);
    wcvt_kernel<<<wcvt_grid, 256>>>(w0, lw0);
    gemm_all_kernel<<<all_grid, 256, GEMM_SMEM>>>(b0, h1);

    // ---- Layer 1 (relu fused into gatex)
    cudaMemsetAsync(out, 0, (size_t)NN * DD * sizeof(float));
    gatex_kernel<<<gatex_grid, 128>>>(h1, gw1, 1);
    wcvt_kernel<<<wcvt_grid, 256>>>(w1, lw1);
    gemm_all_kernel<<<all_grid, 256, GEMM_SMEM>>>(b1, out);
}